// round 11
// baseline (speedup 1.0000x reference)
#include <cuda_runtime.h>
#include <cstdint>

// out[N] = inputs[N, 272] @ weights[272] + bias
// weights[0:16]   = kernel
// weights[16:272] = kernel[i0]*kernel[i3]*w1 + kernel[i1]*kernel[i2]*w2
//
// Strategy: persistent streaming GEMV with TMA bulk staging.
// 2 rows per warp-iteration (2176 B, 16B-aligned bulk copy). Each warp owns
// 3 private smem stages + 3 mbarriers; one elected lane issues
// cp.async.bulk per stage (zero register cost, ~1 issue op), giving 2 full
// groups in flight per warp while a third is computed. Refill is issued
// before the shuffle-reduction so TMA overlaps the dependent chain.

#define UNITS 16
#define DIM   272
#define DIM4  68            // 272 / 4
#define PAIR4 136           // 2 rows in float4 units
#define GRP_BYTES 2176      // 2 rows
#define NSTAGES 3
#define WARPS_PER_BLOCK 8
#define BLOCK_THREADS   256
#define BLOCKS_PER_SM   4
#define NUM_SMS         148
#define FULLMASK 0xffffffffu

// Dynamic smem layout (bytes)
#define ST_STAGES 0
#define STAGES_BYTES (WARPS_PER_BLOCK * NSTAGES * GRP_BYTES)   // 52224
#define ST_W4   STAGES_BYTES                                    // 1088
#define ST_SK   (ST_W4 + DIM * 4)                               // 64
#define ST_MBAR (ST_SK + UNITS * 4)                             // 192
#define SMEM_TOTAL (ST_MBAR + WARPS_PER_BLOCK * NSTAGES * 8)

__device__ __forceinline__ float dot4(float4 a, float4 b) {
    return fmaf(a.x, b.x, fmaf(a.y, b.y, fmaf(a.z, b.z, a.w * b.w)));
}

__device__ __forceinline__ void mbar_init(uint32_t mbar, uint32_t count) {
    asm volatile("mbarrier.init.shared.b64 [%0], %1;" :: "r"(mbar), "r"(count) : "memory");
}
__device__ __forceinline__ void mbar_expect_tx(uint32_t mbar, uint32_t bytes) {
    asm volatile("mbarrier.arrive.expect_tx.shared.b64 _, [%0], %1;"
                 :: "r"(mbar), "r"(bytes) : "memory");
}
__device__ __forceinline__ void mbar_wait(uint32_t mbar, uint32_t parity) {
    uint32_t done;
    asm volatile(
        "{\n\t.reg .pred p;\n\t"
        "mbarrier.try_wait.parity.acquire.cta.shared::cta.b64 p, [%1], %2;\n\t"
        "selp.b32 %0, 1, 0, p;\n\t}"
        : "=r"(done) : "r"(mbar), "r"(parity) : "memory");
    if (!done) {
        asm volatile(
            "{\n\t.reg .pred P1;\n\t"
            "WAIT_LOOP_%=:\n\t"
            "mbarrier.try_wait.parity.acquire.cta.shared::cta.b64 P1, [%0], %1, 0x989680;\n\t"
            "@P1 bra.uni WAIT_DONE_%=;\n\t"
            "bra.uni WAIT_LOOP_%=;\n\t"
            "WAIT_DONE_%=:\n\t}"
            :: "r"(mbar), "r"(parity) : "memory");
    }
}
__device__ __forceinline__ void bulk_cp(uint32_t dst, const void* src, uint32_t mbar) {
    asm volatile(
        "cp.async.bulk.shared::cluster.global.mbarrier::complete_tx::bytes "
        "[%0], [%1], %2, [%3];"
        :: "r"(dst), "l"(src), "r"((uint32_t)GRP_BYTES), "r"(mbar) : "memory");
}
__device__ __forceinline__ void fence_proxy_async_shared() {
    asm volatile("fence.proxy.async.shared::cta;" ::: "memory");
}

__global__ void __launch_bounds__(BLOCK_THREADS, BLOCKS_PER_SM)
linear_gemv_kernel(const float* __restrict__ inputs,
                   const float* __restrict__ kernel,
                   const float* __restrict__ w1,
                   const float* __restrict__ w2,
                   const float* __restrict__ bias,
                   float* __restrict__ out,
                   int n)
{
    extern __shared__ char smem[];
    const uint32_t smem_u32 = (uint32_t)__cvta_generic_to_shared(smem);

    float4* w4 = reinterpret_cast<float4*>(smem + ST_W4);
    float*  w  = reinterpret_cast<float*>(smem + ST_W4);
    float*  sk = reinterpret_cast<float*>(smem + ST_SK);

    const int tid = threadIdx.x;

    if (tid < UNITS) sk[tid] = kernel[tid];
    __syncthreads();

    if (tid < UNITS) w[tid] = sk[tid];
    {
        const int x1 = tid >> 4;
        const int x2 = tid & 15;
        const int a1 = x1 >> 2, b1 = x1 & 3;
        const int a2 = x2 >> 2, b2 = x2 & 3;
        const float pw = sk[4 * a1 + a2] * sk[4 * b1 + b2] * w1[0]
                       + sk[4 * a1 + b2] * sk[4 * b1 + a2] * w2[0];
        w[UNITS + tid] = pw;
    }

    const int warp = tid >> 5;
    const int lane = tid & 31;

    // Warp-private stage addresses + mbarriers.
    const uint32_t stage_base = smem_u32 + (uint32_t)(warp * NSTAGES) * GRP_BYTES;
    const uint32_t mbar_base  = smem_u32 + ST_MBAR + (uint32_t)(warp * NSTAGES) * 8u;
    char* stage_gen = smem + (size_t)(warp * NSTAGES) * GRP_BYTES;

    if (lane == 0) {
        #pragma unroll
        for (int s = 0; s < NSTAGES; ++s) mbar_init(mbar_base + s * 8u, 1);
    }
    __syncwarp();
    __syncthreads();   // weights ready for all, barriers ready

    const float bv = bias[0];

    const int npairs = n >> 1;
    const int stride = gridDim.x * WARPS_PER_BLOCK;
    const int p0     = blockIdx.x * WARPS_PER_BLOCK + warp;

    const float* __restrict__ basef = inputs;

    if (p0 < npairs) {
        // Prime the pipeline: up to NSTAGES groups in flight.
        if (lane == 0) {
            #pragma unroll
            for (int s = 0; s < NSTAGES; ++s) {
                const long long pp = (long long)p0 + (long long)s * stride;
                if (pp < npairs) {
                    const uint32_t mb = mbar_base + s * 8u;
                    mbar_expect_tx(mb, GRP_BYTES);
                    bulk_cp(stage_base + (uint32_t)s * GRP_BYTES,
                            basef + pp * (long long)DIM * 2, mb);
                }
            }
        }

        int cur = 0, ph = 0;
        for (int p = p0; p < npairs; p += stride) {
            mbar_wait(mbar_base + cur * 8u, (uint32_t)ph);

            const float4* __restrict__ s =
                reinterpret_cast<const float4*>(stage_gen + (size_t)cur * GRP_BYTES);

            // Dot products (LDS.128 from stage, conflict-free).
            const float4 a0 = s[lane];
            const float4 a1 = s[lane + 32];
            const float4 a2 = s[lane + 64];
            const float4 a3 = s[lane + 96];
            float4 a4 = make_float4(0.f, 0.f, 0.f, 0.f);
            if (lane < 8) a4 = s[lane + 128];

            float acc0 = dot4(a0, w4[lane]);
            acc0 += dot4(a1, w4[lane + 32]);
            const int wi2 = (lane < 4) ? (lane + 64) : (lane - 4);
            const float d2 = dot4(a2, w4[wi2]);
            float acc1 = (lane < 4) ? 0.0f : d2;
            if (lane < 4) acc0 += d2;
            acc1 += dot4(a3, w4[lane + 28]);
            if (lane < 8) acc1 += dot4(a4, w4[lane + 60]);

            // Refill this stage for group p + NSTAGES*stride BEFORE the
            // reduction chain, so the TMA fetch overlaps it.
            const long long pn = (long long)p + (long long)NSTAGES * stride;
            if (lane == 0 && pn < npairs) {
                fence_proxy_async_shared();
                const uint32_t mb = mbar_base + cur * 8u;
                mbar_expect_tx(mb, GRP_BYTES);
                bulk_cp(stage_base + (uint32_t)cur * GRP_BYTES,
                        basef + pn * (long long)DIM * 2, mb);
            }

            acc0 += __shfl_xor_sync(FULLMASK, acc0, 16);
            acc1 += __shfl_xor_sync(FULLMASK, acc1, 16);
            float v = (lane & 16) ? acc1 : acc0;
            v += __shfl_xor_sync(FULLMASK, v, 8);
            v += __shfl_xor_sync(FULLMASK, v, 4);
            v += __shfl_xor_sync(FULLMASK, v, 2);
            v += __shfl_xor_sync(FULLMASK, v, 1);

            if (lane == 0)  out[p * 2]     = v + bv;
            if (lane == 16) out[p * 2 + 1] = v + bv;

            if (++cur == NSTAGES) { cur = 0; ph ^= 1; }
        }
    }

    // Odd trailing row (n odd): one warp handles it scalar-style.
    if ((n & 1) && blockIdx.x == 0 && warp == 0) {
        const int r = n - 1;
        const float* __restrict__ row = inputs + (size_t)r * DIM;
        float acc = 0.0f;
        for (int j = lane; j < DIM; j += 32)
            acc = fmaf(row[j], w[j], acc);
        #pragma unroll
        for (int off = 16; off > 0; off >>= 1)
            acc += __shfl_xor_sync(FULLMASK, acc, off);
        if (lane == 0) out[r] = acc + bv;
    }
}

extern "C" void kernel_launch(void* const* d_in, const int* in_sizes, int n_in,
                              void* d_out, int out_size)
{
    const float* inputs = (const float*)d_in[0];
    const float* kernel = (const float*)d_in[1];
    const float* w1     = (const float*)d_in[2];
    const float* w2     = (const float*)d_in[3];
    const float* bias   = (const float*)d_in[4];
    float* out = (float*)d_out;

    static bool attr_set = false;
    if (!attr_set) {
        cudaFuncSetAttribute(linear_gemv_kernel,
                             cudaFuncAttributeMaxDynamicSharedMemorySize, SMEM_TOTAL);
        attr_set = true;
    }

    const int n = out_size;
    int blocks = NUM_SMS * BLOCKS_PER_SM;          // persistent fill
    const int groups = (n / 2 + WARPS_PER_BLOCK - 1) / WARPS_PER_BLOCK;
    if (blocks > groups && groups > 0) blocks = groups;
    if (blocks < 1) blocks = 1;
    linear_gemv_kernel<<<blocks, BLOCK_THREADS, SMEM_TOTAL>>>(
        inputs, kernel, w1, w2, bias, out, n);
}

// round 13
// speedup vs baseline: 1.3261x; 1.3261x over previous
#include <cuda_runtime.h>

// out[N] = inputs[N, 272] @ weights[272] + bias
// weights[0:16]   = kernel
// weights[16:272] = kernel[i0]*kernel[i3]*w1 + kernel[i1]*kernel[i2]*w2
//
// Strategy: persistent HBM-streaming GEMV (R6 structure). 2 rows per
// warp-iteration (2176 B = 17 lines, 128B-aligned; 4 full-warp 512B loads
// + one 8-lane tail), register double-buffered prefetch. 128-thread blocks
// so the 55-reg budget packs 9 blocks/SM (36 warps) instead of 4x256 (32).

#define UNITS 16
#define DIM   272
#define DIM4  68           // 272 / 4
#define PAIR4 136          // 2 rows in float4 units
#define WARPS_PER_BLOCK 4
#define BLOCK_THREADS   128
#define BLOCKS_PER_SM   9
#define NUM_SMS         148
#define FULLMASK 0xffffffffu

__device__ __forceinline__ float dot4(float4 a, float4 b) {
    return fmaf(a.x, b.x, fmaf(a.y, b.y, fmaf(a.z, b.z, a.w * b.w)));
}

struct Grp {
    float4 a0, a1, a2, a3, a4;
};

__device__ __forceinline__ Grp load_grp(const float4* __restrict__ base,
                                        int pair, int lane)
{
    const float4* __restrict__ in = base + (size_t)pair * PAIR4;
    Grp g;
    g.a0 = __ldcs(in + lane);         // j   0..31  row0
    g.a1 = __ldcs(in + lane + 32);    // j  32..63  row0
    g.a2 = __ldcs(in + lane + 64);    // j  64..95  split @68
    g.a3 = __ldcs(in + lane + 96);    // j  96..127 row1
    g.a4 = make_float4(0.f, 0.f, 0.f, 0.f);
    if (lane < 8) g.a4 = __ldcs(in + lane + 128);  // j 128..135 row1
    return g;
}

__device__ __forceinline__ void compute_grp(const Grp& g,
                                            const float4* __restrict__ w4,
                                            float bv, int lane,
                                            float* __restrict__ out, int r0)
{
    float acc0 = dot4(g.a0, w4[lane]);
    acc0 += dot4(g.a1, w4[lane + 32]);

    // j = lane+64: row0 col (lane+64) if lane<4, else row1 col (lane-4)
    const int wi2 = (lane < 4) ? (lane + 64) : (lane - 4);
    const float d2 = dot4(g.a2, w4[wi2]);
    float acc1 = (lane < 4) ? 0.0f : d2;
    if (lane < 4) acc0 += d2;

    acc1 += dot4(g.a3, w4[lane + 28]);               // col = lane+96-68
    if (lane < 8) acc1 += dot4(g.a4, w4[lane + 60]); // col = lane+128-68

    acc0 += __shfl_xor_sync(FULLMASK, acc0, 16);
    acc1 += __shfl_xor_sync(FULLMASK, acc1, 16);
    float v = (lane & 16) ? acc1 : acc0;
    v += __shfl_xor_sync(FULLMASK, v, 8);
    v += __shfl_xor_sync(FULLMASK, v, 4);
    v += __shfl_xor_sync(FULLMASK, v, 2);
    v += __shfl_xor_sync(FULLMASK, v, 1);

    if (lane == 0)  out[r0]     = v + bv;
    if (lane == 16) out[r0 + 1] = v + bv;
}

__global__ void __launch_bounds__(BLOCK_THREADS)
linear_gemv_kernel(const float* __restrict__ inputs,
                   const float* __restrict__ kernel,
                   const float* __restrict__ w1,
                   const float* __restrict__ w2,
                   const float* __restrict__ bias,
                   float* __restrict__ out,
                   int n)
{
    __shared__ float4 w4[DIM4];
    __shared__ float  sk[UNITS];

    const int tid = threadIdx.x;

    if (tid < UNITS) sk[tid] = kernel[tid];
    __syncthreads();

    float* w = reinterpret_cast<float*>(w4);
    if (tid < UNITS) w[tid] = sk[tid];
    // 256 pair weights built by 128 threads: 2 each.
    #pragma unroll
    for (int pidx = tid; pidx < 256; pidx += BLOCK_THREADS) {
        const int x1 = pidx >> 4;
        const int x2 = pidx & 15;
        const int a1 = x1 >> 2, b1 = x1 & 3;
        const int a2 = x2 >> 2, b2 = x2 & 3;
        const float pw = sk[4 * a1 + a2] * sk[4 * b1 + b2] * w1[0]
                       + sk[4 * a1 + b2] * sk[4 * b1 + a2] * w2[0];
        w[UNITS + pidx] = pw;
    }
    __syncthreads();

    const float bv = bias[0];

    const int warp   = tid >> 5;
    const int lane   = tid & 31;
    const int npairs = n >> 1;                     // full 2-row groups
    const int stride = gridDim.x * WARPS_PER_BLOCK;
    int p = blockIdx.x * WARPS_PER_BLOCK + warp;

    const float4* __restrict__ base = reinterpret_cast<const float4*>(inputs);

    if (p < npairs) {
        Grp cur = load_grp(base, p, lane);
        while (true) {
            const int pn = p + stride;
            if (pn < npairs) {
                Grp nxt = load_grp(base, pn, lane);   // prefetch next group
                compute_grp(cur, w4, bv, lane, out, p * 2);
                cur = nxt;
                p = pn;
            } else {
                compute_grp(cur, w4, bv, lane, out, p * 2);
                break;
            }
        }
    }

    // Odd trailing row (n odd): one warp handles it scalar-style.
    if ((n & 1) && blockIdx.x == 0 && warp == 0) {
        const int r = n - 1;
        const float* __restrict__ row = inputs + (size_t)r * DIM;
        float acc = 0.0f;
        for (int j = lane; j < DIM; j += 32)
            acc = fmaf(row[j], w[j], acc);
        #pragma unroll
        for (int off = 16; off > 0; off >>= 1)
            acc += __shfl_xor_sync(FULLMASK, acc, off);
        if (lane == 0) out[r] = acc + bv;
    }
}

extern "C" void kernel_launch(void* const* d_in, const int* in_sizes, int n_in,
                              void* d_out, int out_size)
{
    const float* inputs = (const float*)d_in[0];
    const float* kernel = (const float*)d_in[1];
    const float* w1     = (const float*)d_in[2];
    const float* w2     = (const float*)d_in[3];
    const float* bias   = (const float*)d_in[4];
    float* out = (float*)d_out;

    const int n = out_size;
    int blocks = NUM_SMS * BLOCKS_PER_SM;          // persistent fill
    const int groups = (n / 2 + WARPS_PER_BLOCK - 1) / WARPS_PER_BLOCK;
    if (blocks > groups && groups > 0) blocks = groups;
    if (blocks < 1) blocks = 1;
    linear_gemv_kernel<<<blocks, BLOCK_THREADS>>>(inputs, kernel, w1, w2, bias, out, n);
}

// round 14
// speedup vs baseline: 1.3593x; 1.0251x over previous
#include <cuda_runtime.h>

// out[N] = inputs[N, 272] @ weights[272] + bias
// weights[0:16]   = kernel
// weights[16:272] = kernel[i0]*kernel[i3]*w1 + kernel[i1]*kernel[i2]*w2
//
// FINAL (R6 configuration — measured optimum at 80.0us, DRAM 83.6%).
// Persistent HBM-streaming GEMV. 2 rows per warp-iteration (footprint =
// 2176 B = exactly 17 cache lines, 128B-aligned; 4 full-warp 512B float4
// loads + one 8-lane tail). Grid-stride over groups with register
// double-buffering: next group's loads issue before the current group's
// FMA/shuffle chain, hiding the dependent-reduction latency.
// 256-thread blocks, natural 55 regs -> 4 blocks/SM; all perturbations of
// occupancy / pipeline depth / staging mechanism measured worse (R5-R13).

#define UNITS 16
#define DIM   272
#define DIM4  68           // 272 / 4
#define PAIR4 136          // 2 rows in float4 units
#define WARPS_PER_BLOCK 8
#define BLOCK_THREADS   256
#define BLOCKS_PER_SM   4
#define NUM_SMS         148
#define FULLMASK 0xffffffffu

__device__ __forceinline__ float dot4(float4 a, float4 b) {
    return fmaf(a.x, b.x, fmaf(a.y, b.y, fmaf(a.z, b.z, a.w * b.w)));
}

struct Grp {
    float4 a0, a1, a2, a3, a4;
};

__device__ __forceinline__ Grp load_grp(const float4* __restrict__ base,
                                        int pair, int lane)
{
    const float4* __restrict__ in = base + (size_t)pair * PAIR4;
    Grp g;
    g.a0 = __ldcs(in + lane);         // j   0..31  row0
    g.a1 = __ldcs(in + lane + 32);    // j  32..63  row0
    g.a2 = __ldcs(in + lane + 64);    // j  64..95  split @68
    g.a3 = __ldcs(in + lane + 96);    // j  96..127 row1
    g.a4 = make_float4(0.f, 0.f, 0.f, 0.f);
    if (lane < 8) g.a4 = __ldcs(in + lane + 128);  // j 128..135 row1
    return g;
}

__device__ __forceinline__ void compute_grp(const Grp& g,
                                            const float4* __restrict__ w4,
                                            float bv, int lane,
                                            float* __restrict__ out, int r0)
{
    float acc0 = dot4(g.a0, w4[lane]);
    acc0 += dot4(g.a1, w4[lane + 32]);

    // j = lane+64: row0 col (lane+64) if lane<4, else row1 col (lane-4)
    const int wi2 = (lane < 4) ? (lane + 64) : (lane - 4);
    const float d2 = dot4(g.a2, w4[wi2]);
    float acc1 = (lane < 4) ? 0.0f : d2;
    if (lane < 4) acc0 += d2;

    acc1 += dot4(g.a3, w4[lane + 28]);               // col = lane+96-68
    if (lane < 8) acc1 += dot4(g.a4, w4[lane + 60]); // col = lane+128-68

    acc0 += __shfl_xor_sync(FULLMASK, acc0, 16);
    acc1 += __shfl_xor_sync(FULLMASK, acc1, 16);
    float v = (lane & 16) ? acc1 : acc0;
    v += __shfl_xor_sync(FULLMASK, v, 8);
    v += __shfl_xor_sync(FULLMASK, v, 4);
    v += __shfl_xor_sync(FULLMASK, v, 2);
    v += __shfl_xor_sync(FULLMASK, v, 1);

    if (lane == 0)  out[r0]     = v + bv;
    if (lane == 16) out[r0 + 1] = v + bv;
}

__global__ void __launch_bounds__(BLOCK_THREADS)
linear_gemv_kernel(const float* __restrict__ inputs,
                   const float* __restrict__ kernel,
                   const float* __restrict__ w1,
                   const float* __restrict__ w2,
                   const float* __restrict__ bias,
                   float* __restrict__ out,
                   int n)
{
    __shared__ float4 w4[DIM4];
    __shared__ float  sk[UNITS];

    const int tid = threadIdx.x;

    if (tid < UNITS) sk[tid] = kernel[tid];
    __syncthreads();

    float* w = reinterpret_cast<float*>(w4);
    if (tid < UNITS) w[tid] = sk[tid];
    {
        const int x1 = tid >> 4;
        const int x2 = tid & 15;
        const int a1 = x1 >> 2, b1 = x1 & 3;
        const int a2 = x2 >> 2, b2 = x2 & 3;
        const float pw = sk[4 * a1 + a2] * sk[4 * b1 + b2] * w1[0]
                       + sk[4 * a1 + b2] * sk[4 * b1 + a2] * w2[0];
        w[UNITS + tid] = pw;
    }
    __syncthreads();

    const float bv = bias[0];

    const int warp   = tid >> 5;
    const int lane   = tid & 31;
    const int npairs = n >> 1;                     // full 2-row groups
    const int stride = gridDim.x * WARPS_PER_BLOCK;
    int p = blockIdx.x * WARPS_PER_BLOCK + warp;

    const float4* __restrict__ base = reinterpret_cast<const float4*>(inputs);

    if (p < npairs) {
        Grp cur = load_grp(base, p, lane);
        while (true) {
            const int pn = p + stride;
            if (pn < npairs) {
                Grp nxt = load_grp(base, pn, lane);   // prefetch next group
                compute_grp(cur, w4, bv, lane, out, p * 2);
                cur = nxt;
                p = pn;
            } else {
                compute_grp(cur, w4, bv, lane, out, p * 2);
                break;
            }
        }
    }

    // Odd trailing row (n odd): one warp handles it scalar-style.
    if ((n & 1) && blockIdx.x == 0 && warp == 0) {
        const int r = n - 1;
        const float* __restrict__ row = inputs + (size_t)r * DIM;
        float acc = 0.0f;
        for (int j = lane; j < DIM; j += 32)
            acc = fmaf(row[j], w[j], acc);
        #pragma unroll
        for (int off = 16; off > 0; off >>= 1)
            acc += __shfl_xor_sync(FULLMASK, acc, off);
        if (lane == 0) out[r] = acc + bv;
    }
}

extern "C" void kernel_launch(void* const* d_in, const int* in_sizes, int n_in,
                              void* d_out, int out_size)
{
    const float* inputs = (const float*)d_in[0];
    const float* kernel = (const float*)d_in[1];
    const float* w1     = (const float*)d_in[2];
    const float* w2     = (const float*)d_in[3];
    const float* bias   = (const float*)d_in[4];
    float* out = (float*)d_out;

    const int n = out_size;
    int blocks = NUM_SMS * BLOCKS_PER_SM;          // persistent fill
    const int groups = (n / 2 + WARPS_PER_BLOCK - 1) / WARPS_PER_BLOCK;
    if (blocks > groups && groups > 0) blocks = groups;
    if (blocks < 1) blocks = 1;
    linear_gemv_kernel<<<blocks, BLOCK_THREADS>>>(inputs, kernel, w1, w2, bias, out, n);
}